// round 15
// baseline (speedup 1.0000x reference)
#include <cuda_runtime.h>
#include <cuda_fp16.h>
#include <math.h>

// Problem constants
#define BSZ  2
#define NND  2048
#define FIN  128
#define H1C  8
#define HF1  512      // H1*F1
#define F2C  64
#define MROW 4096     // BSZ*NND
#define MAXN 128      // neighbor cap (binomial mean ~41)

// ---------------- scratch (static device memory; no allocs) ----------------
__device__ __half g_xh   [MROW*FIN];        // fp16 x
__device__ __half g_wh1  [1024*FIN];        // fp16 [W1 ; Wsk1]
__device__ __half g_wh2  [128*HF1];         // fp16 [W2 ; Wsk2]
__device__ __half g_proj1h[MROW*HF1];       // fp16 proj1 (gather operand)
__device__ float  g_skip1 [MROW*HF1];
__device__ __half g_h1h  [MROW*HF1];        // fp16 h1 (gemm2 A operand)
__device__ __half g_proj2h[MROW*F2C];
__device__ float  g_skip2 [MROW*F2C];
__device__ float  g_ssrc1 [MROW*H1C];       // [m][h]
__device__ float  g_stgt1 [MROW*H1C];       // [m][h]  (row-contiguous, 32B)
__device__ float  g_ssrc2 [MROW];
__device__ float  g_stgt2 [MROW];
__device__ int    g_nbrs[MROW*MAXN];
__device__ int    g_cnt [MROW];

// ---------------- mma / ldmatrix helpers -----------------------------------
__device__ __forceinline__ void mma_16816(float c[4], const unsigned a[4],
                                          unsigned b0, unsigned b1) {
    asm volatile(
        "mma.sync.aligned.m16n8k16.row.col.f32.f16.f16.f32 "
        "{%0,%1,%2,%3}, {%4,%5,%6,%7}, {%8,%9}, {%0,%1,%2,%3};"
        : "+f"(c[0]), "+f"(c[1]), "+f"(c[2]), "+f"(c[3])
        : "r"(a[0]), "r"(a[1]), "r"(a[2]), "r"(a[3]), "r"(b0), "r"(b1));
}
__device__ __forceinline__ void ldsm4(unsigned r[4], const void* p) {
    unsigned addr = (unsigned)__cvta_generic_to_shared(p);
    asm volatile("ldmatrix.sync.aligned.m8n8.x4.shared.b16 {%0,%1,%2,%3}, [%4];"
                 : "=r"(r[0]), "=r"(r[1]), "=r"(r[2]), "=r"(r[3]) : "r"(addr));
}

// ---------------- prep: fp32 -> fp16 (split into 2 launches) ---------------
__device__ __forceinline__ void cvt_store(const float4* s, __half* d) {
    float4 v = *s;
    __half2 h01 = __floats2half2_rn(v.x, v.y);
    __half2 h23 = __floats2half2_rn(v.z, v.w);
    uint2 pk;
    pk.x = *reinterpret_cast<unsigned*>(&h01);
    pk.y = *reinterpret_cast<unsigned*>(&h23);
    *reinterpret_cast<uint2*>(d) = pk;
}
__global__ void prep_x(const float* __restrict__ x) {
    int i = blockIdx.x * blockDim.x + threadIdx.x;   // 131072 float4
    cvt_store((const float4*)x + i, g_xh + i * 4);
}
__global__ void prep_w(const float* __restrict__ W1, const float* __restrict__ Ws1,
                       const float* __restrict__ W2, const float* __restrict__ Ws2) {
    int i = blockIdx.x * blockDim.x + threadIdx.x;   // 49152 float4
    const float4* s; __half* d;
    if      (i < 16384) { s = (const float4*)W1  + i;           d = g_wh1 + i*4; }
    else if (i < 32768) { s = (const float4*)Ws1 + (i-16384);   d = g_wh1 + 65536 + (i-16384)*4; }
    else if (i < 40960) { s = (const float4*)W2  + (i-32768);   d = g_wh2 + (i-32768)*4; }
    else                { s = (const float4*)Ws2 + (i-40960);   d = g_wh2 + 32768 + (i-40960)*4; }
    cvt_store(s, d);
}

// ============ fused: layer-1 mma GEMM (+fp16 proj, +scores) ∥ nbr build ====
__global__ void __launch_bounds__(256) fused1(
    const float* __restrict__ asrc, const float* __restrict__ atgt,
    const float* __restrict__ adj) {
    __shared__ __align__(16) char As[16384];   // 128 rows x 128B, swizzled
    __shared__ __align__(16) char Bs[16384];
    __shared__ unsigned int words[64];

    const int tid  = threadIdx.x;
    const int lane = tid & 31;
    const int wid  = tid >> 5;

    if (blockIdx.x >= 256) {
        // ---------------- neighbor build (batched loads, MLP=8) ------------
        const int bid = (int)blockIdx.x - 256;
        const int i   = bid & (NND - 1);
        const int b   = bid >> 11;
        const int row = b * NND + i;
        const size_t arow = (size_t)row * NND;
        float av[8];
        #pragma unroll
        for (int it = 0; it < 8; ++it)
            av[it] = adj[arow + (((wid << 3) + it) << 5) + lane];
        #pragma unroll
        for (int it = 0; it < 8; ++it) {
            unsigned m = __ballot_sync(0xffffffffu, av[it] != 0.0f);
            if (lane == 0) words[(wid << 3) + it] = m;
        }
        __syncthreads();
        if (wid == 0) {
            int base = 0;
            #pragma unroll
            for (int r = 0; r < 2; ++r) {
                unsigned w = words[(r << 5) + lane];
                int c = __popc(w);
                int inc = c;
                #pragma unroll
                for (int d = 1; d < 32; d <<= 1) {
                    int v = __shfl_up_sync(0xffffffffu, inc, d);
                    if (lane >= d) inc += v;
                }
                int start = base + inc - c;
                int jb = ((r << 5) + lane) << 5;
                while (w) {
                    int bit = __ffs(w) - 1;
                    w &= w - 1;
                    if (start < MAXN) g_nbrs[(size_t)row * MAXN + start] = jb + bit;
                    ++start;
                }
                base += __shfl_sync(0xffffffffu, inc, 31);
            }
            if (lane == 0) g_cnt[row] = (base < MAXN) ? base : MAXN;
        }
        return;
    }

    // ---------------- mma GEMM tile ----------------
    const int bx = blockIdx.x & 7;
    const int by = blockIdx.x >> 3;
    const int m0 = by << 7;
    const int n0 = bx << 7;
    const int wm = wid & 3;              // 4 m-warps (32 rows each)
    const int wn = wid >> 2;             // 2 n-warps (64 cols each)

    float acc[2][8][4];
    #pragma unroll
    for (int mt = 0; mt < 2; ++mt)
        #pragma unroll
        for (int nt = 0; nt < 8; ++nt)
            #pragma unroll
            for (int c = 0; c < 4; ++c) acc[mt][nt][c] = 0.f;

    const uint4* __restrict__ xg = reinterpret_cast<const uint4*>(g_xh);
    const uint4* __restrict__ wg = reinterpret_cast<const uint4*>(g_wh1);

    #pragma unroll
    for (int kc = 0; kc < 2; ++kc) {
        #pragma unroll
        for (int it = 0; it < 4; ++it) {
            int idx = tid + (it << 8);           // 0..1023
            int r   = idx >> 3;                  // row 0..127
            int cb  = idx & 7;                   // 16B chunk 0..7
            uint4 a = xg[(size_t)(m0 + r) * 16 + kc * 8 + cb];
            *reinterpret_cast<uint4*>(As + r * 128 + ((cb << 4) ^ ((r & 7) << 4))) = a;
            uint4 b = wg[(size_t)(n0 + r) * 16 + kc * 8 + cb];
            *reinterpret_cast<uint4*>(Bs + r * 128 + ((cb << 4) ^ ((r & 7) << 4))) = b;
        }
        __syncthreads();

        #pragma unroll
        for (int ks = 0; ks < 4; ++ks) {
            const int kb = (ks << 5) + (lane & 16);
            unsigned af[2][4], bf[4][4];
            #pragma unroll
            for (int mt = 0; mt < 2; ++mt) {
                int r = (wm << 5) + (mt << 4) + (lane & 15);
                ldsm4(af[mt], As + r * 128 + (kb ^ ((r & 7) << 4)));
            }
            #pragma unroll
            for (int bt = 0; bt < 4; ++bt) {
                int r = (wn << 6) + (bt << 4) + (lane & 15);
                ldsm4(bf[bt], Bs + r * 128 + (kb ^ ((r & 7) << 4)));
            }
            #pragma unroll
            for (int mt = 0; mt < 2; ++mt)
                #pragma unroll
                for (int nt = 0; nt < 8; ++nt)
                    mma_16816(acc[mt][nt], af[mt],
                              bf[nt >> 1][nt & 1], bf[nt >> 1][2 + (nt & 1)]);
        }
        __syncthreads();
    }

    // ---------------- epilogue ----------------
    const int q    = lane >> 2;          // row-in-group
    const int tcol = (lane & 3) << 1;    // col pair base
    if (bx < 4) {
        const int h = (bx << 1) + wn;    // head covered by this warp
        float2 s2[8], t2[8];
        #pragma unroll
        for (int nt = 0; nt < 8; ++nt) {
            s2[nt] = *reinterpret_cast<const float2*>(asrc + h * 64 + (nt << 3) + tcol);
            t2[nt] = *reinterpret_cast<const float2*>(atgt + h * 64 + (nt << 3) + tcol);
        }
        #pragma unroll
        for (int mt = 0; mt < 2; ++mt) {
            const int mlo = m0 + (wm << 5) + (mt << 4) + q;
            const int mhi = mlo + 8;
            float ssl = 0.f, stl = 0.f, ssh = 0.f, sth = 0.f;
            #pragma unroll
            for (int nt = 0; nt < 8; ++nt) {
                const float* c = acc[mt][nt];
                const int col = h * 64 + (nt << 3) + tcol;
                __half2 hl = __floats2half2_rn(c[0], c[1]);
                __half2 hh = __floats2half2_rn(c[2], c[3]);
                *reinterpret_cast<unsigned*>(g_proj1h + (size_t)mlo * HF1 + col)
                    = *reinterpret_cast<unsigned*>(&hl);
                *reinterpret_cast<unsigned*>(g_proj1h + (size_t)mhi * HF1 + col)
                    = *reinterpret_cast<unsigned*>(&hh);
                ssl += c[0]*s2[nt].x + c[1]*s2[nt].y;
                stl += c[0]*t2[nt].x + c[1]*t2[nt].y;
                ssh += c[2]*s2[nt].x + c[3]*s2[nt].y;
                sth += c[2]*t2[nt].x + c[3]*t2[nt].y;
            }
            #pragma unroll
            for (int d = 1; d < 4; d <<= 1) {
                ssl += __shfl_xor_sync(0xffffffffu, ssl, d);
                stl += __shfl_xor_sync(0xffffffffu, stl, d);
                ssh += __shfl_xor_sync(0xffffffffu, ssh, d);
                sth += __shfl_xor_sync(0xffffffffu, sth, d);
            }
            if ((lane & 3) == 0) {
                g_ssrc1[mlo * H1C + h] = ssl;
                g_ssrc1[mhi * H1C + h] = ssh;
                g_stgt1[mlo * H1C + h] = stl;
                g_stgt1[mhi * H1C + h] = sth;
            }
        }
    } else {
        #pragma unroll
        for (int mt = 0; mt < 2; ++mt) {
            const int mlo = m0 + (wm << 5) + (mt << 4) + q;
            const int mhi = mlo + 8;
            #pragma unroll
            for (int nt = 0; nt < 8; ++nt) {
                const float* c = acc[mt][nt];
                const int col = ((bx - 4) << 7) + (wn << 6) + (nt << 3) + tcol;
                *reinterpret_cast<float2*>(g_skip1 + (size_t)mlo * HF1 + col)
                    = make_float2(c[0], c[1]);
                *reinterpret_cast<float2*>(g_skip1 + (size_t)mhi * HF1 + col)
                    = make_float2(c[2], c[3]);
            }
        }
    }
}

// ========== layer-1 attention: no-max softmax, prefetched MLP=8 gather =====
// Phase 0: nbr offsets + 8-head score vectors -> smem; pad lists to mult of 8
// (pad noff = valid row, pad weight = 0 -> exact no-op FMAs).
// Prefetch first 8 gather rows BEFORE softmax (addresses independent of wts).
__global__ void __launch_bounds__(128) att1_kernel(const float* __restrict__ bias) {
    __shared__ int     noff[MAXN];              // (brow+j)<<7 (uint2 row base)
    __shared__ float   stv[MAXN][9];            // 8 head scores + pad
    __shared__ __half2 wts2[H1C][MAXN];

    const int i    = blockIdx.x;
    const int b    = blockIdx.y;
    const int tid  = threadIdx.x;
    const int lane = tid & 31;
    const int wid  = tid >> 5;
    const int row  = b * NND + i;
    const int brow = b * NND;

    const int cnt  = g_cnt[row];
    const int cnt8 = (cnt + 7) & ~7;            // <= MAXN
    const __half2 z = __float2half2_rn(0.f);

    for (int n = tid; n < cnt; n += 128) {
        int j = g_nbrs[(size_t)row * MAXN + n];
        noff[n] = (brow + j) << 7;
        const float4* sp = reinterpret_cast<const float4*>(
            g_stgt1 + (size_t)(brow + j) * H1C);
        float4 s0 = sp[0];
        float4 s1 = sp[1];
        stv[n][0] = s0.x; stv[n][1] = s0.y; stv[n][2] = s0.z; stv[n][3] = s0.w;
        stv[n][4] = s1.x; stv[n][5] = s1.y; stv[n][6] = s1.z; stv[n][7] = s1.w;
    }
    if (tid < 8) {                               // zero-pad to multiple of 8
        int n = cnt + tid;
        if (n < MAXN) {
            noff[n] = brow << 7;                 // valid row, weight = 0
            #pragma unroll
            for (int h2 = 0; h2 < H1C; ++h2) wts2[h2][n] = z;
        }
    }
    __syncthreads();

    // prefetch first 8 gather rows (independent of softmax)
    const int h = tid >> 4;
    const uint2* __restrict__ ph = reinterpret_cast<const uint2*>(g_proj1h);
    uint2 r[8];
    #pragma unroll
    for (int k = 0; k < 8; ++k) r[k] = ph[noff[k] + tid];

    // softmax without max-shift (|scores| << 88 analytically)
    #pragma unroll
    for (int hh = 0; hh < 2; ++hh) {
        const int hd = (wid << 1) + hh;
        const float si = g_ssrc1[row * H1C + hd];
        float e[4];
        float sum = 0.f;
        #pragma unroll
        for (int s = 0; s < 4; ++s) {
            int n = lane + (s << 5);
            float ex = 0.f;
            if (n < cnt) {
                float t = si + stv[n][hd];
                t = (t > 0.f) ? t : 0.2f * t;    // leaky_relu(0.2)
                ex = __expf(t);
            }
            e[s] = ex;
            sum += ex;
        }
        #pragma unroll
        for (int d = 16; d; d >>= 1)
            sum += __shfl_xor_sync(0xffffffffu, sum, d);
        float inv = 1.0f / sum;
        #pragma unroll
        for (int s = 0; s < 4; ++s) {
            int n = lane + (s << 5);
            if (n < cnt) wts2[hd][n] = __float2half2_rn(e[s] * inv);
        }
    }
    __syncthreads();

    // gather: unguarded 8-wide pipeline over padded list
    __half2 A[4] = {z,z,z,z}, B[4] = {z,z,z,z};
    for (int n = 0; n < cnt8; n += 8) {
        uint2 r2[8];
        const bool more = (n + 8) < cnt8;
        if (more) {
            #pragma unroll
            for (int k = 0; k < 8; ++k) r2[k] = ph[noff[n + 8 + k] + tid];
        }
        #pragma unroll
        for (int k = 0; k < 8; ++k) {
            __half2 w = wts2[h][n + k];
            A[k & 3] = __hfma2(w, *reinterpret_cast<__half2*>(&r[k].x), A[k & 3]);
            B[k & 3] = __hfma2(w, *reinterpret_cast<__half2*>(&r[k].y), B[k & 3]);
        }
        if (more) {
            #pragma unroll
            for (int k = 0; k < 8; ++k) r[k] = r2[k];
        }
    }
    float2 fa0 = __half22float2(A[0]), fa1 = __half22float2(A[1]);
    float2 fa2 = __half22float2(A[2]), fa3 = __half22float2(A[3]);
    float2 fb0 = __half22float2(B[0]), fb1 = __half22float2(B[1]);
    float2 fb2 = __half22float2(B[2]), fb3 = __half22float2(B[3]);
    const int p = tid << 2;
    float4 sk = *reinterpret_cast<const float4*>(g_skip1 + (size_t)row * HF1 + p);
    float4 bb = *reinterpret_cast<const float4*>(bias + p);
    float4 o;
    o.x = (fa0.x + fa1.x) + (fa2.x + fa3.x) + sk.x + bb.x;
    o.y = (fa0.y + fa1.y) + (fa2.y + fa3.y) + sk.y + bb.y;
    o.z = (fb0.x + fb1.x) + (fb2.x + fb3.x) + sk.z + bb.z;
    o.w = (fb0.y + fb1.y) + (fb2.y + fb3.y) + sk.w + bb.w;
    o.x = (o.x > 0.f) ? o.x : (__expf(o.x) - 1.f);
    o.y = (o.y > 0.f) ? o.y : (__expf(o.y) - 1.f);
    o.z = (o.z > 0.f) ? o.z : (__expf(o.z) - 1.f);
    o.w = (o.w > 0.f) ? o.w : (__expf(o.w) - 1.f);
    __half2 h01 = __floats2half2_rn(o.x, o.y);
    __half2 h23 = __floats2half2_rn(o.z, o.w);
    uint2 pk;
    pk.x = *reinterpret_cast<unsigned*>(&h01);
    pk.y = *reinterpret_cast<unsigned*>(&h23);
    *reinterpret_cast<uint2*>(g_h1h + (size_t)row * HF1 + p) = pk;
}

// ===== layer-2 mma GEMM: 8 warps (16x32 warp tile), double-buffered ========
__global__ void __launch_bounds__(256) gemm2_kernel(
    const float* __restrict__ a_src, const float* __restrict__ a_tgt) {
    __shared__ __align__(16) char As[2][8192];   // 64 rows x 128B each
    __shared__ __align__(16) char Bs[2][8192];
    __shared__ float sred_ss[64], sred_st[64];

    const int tid  = threadIdx.x;
    const int lane = tid & 31;
    const int wid  = tid >> 5;           // 0..7
    const int wm   = wid & 3;            // 16-row group
    const int wn   = wid >> 2;           // 32-col group
    const int m0   = blockIdx.y << 6;
    const int side = blockIdx.x;         // 0 proj, 1 skip

    float acc[4][4];
    #pragma unroll
    for (int nt = 0; nt < 4; ++nt)
        #pragma unroll
        for (int c = 0; c < 4; ++c) acc[nt][c] = 0.f;

    const uint4* __restrict__ ag = reinterpret_cast<const uint4*>(g_h1h);
    const uint4* __restrict__ bg = reinterpret_cast<const uint4*>(g_wh2);

    const int fr = tid >> 3;             // 0..31; rows fr, fr+32
    const int fc = tid & 7;              // 16B chunk 0..7
    uint4 pa[2], pb[2];

    #pragma unroll
    for (int it = 0; it < 2; ++it) {
        int r = fr + (it << 5);
        pa[it] = ag[(size_t)(m0 + r) * 64 + fc];
        pb[it] = bg[(size_t)(side * 64 + r) * 64 + fc];
    }
    #pragma unroll
    for (int it = 0; it < 2; ++it) {
        int r = fr + (it << 5);
        int off = r * 128 + ((fc << 4) ^ ((r & 7) << 4));
        *reinterpret_cast<uint4*>(As[0] + off) = pa[it];
        *reinterpret_cast<uint4*>(Bs[0] + off) = pb[it];
    }
    __syncthreads();

    #pragma unroll
    for (int kc = 0; kc < 8; ++kc) {
        const int cur = kc & 1;
        if (kc < 7) {
            #pragma unroll
            for (int it = 0; it < 2; ++it) {
                int r = fr + (it << 5);
                pa[it] = ag[(size_t)(m0 + r) * 64 + (kc + 1) * 8 + fc];
                pb[it] = bg[(size_t)(side * 64 + r) * 64 + (kc + 1) * 8 + fc];
            }
        }
        #pragma unroll
        for (int ks = 0; ks < 4; ++ks) {
            const int kb = (ks << 5) + (lane & 16);
            unsigned af[4], bf[2][4];
            {
                int r = (wm << 4) + (lane & 15);
                ldsm4(af, As[cur] + r * 128 + (kb ^ ((r & 7) << 4)));
            }
            #pragma unroll
            for (int bt = 0; bt < 2; ++bt) {
                int r = (wn << 5) + (bt << 4) + (lane & 15);
                ldsm4(bf[bt], Bs[cur] + r * 128 + (kb ^ ((r & 7) << 4)));
            }
            #pragma unroll
            for (int nt = 0; nt < 4; ++nt)
                mma_16816(acc[nt], af,
                          bf[nt >> 1][nt & 1], bf[nt >> 1][2 + (nt & 1)]);
        }
        if (kc < 7) {
            #pragma unroll
            for (int it = 0; it < 2; ++it) {
                int r = fr + (it << 5);
                int off = r * 128 + ((fc << 4) ^ ((r & 7) << 4));
                *reinterpret_cast<uint4*>(As[cur ^ 1] + off) = pa[it];
                *reinterpret_cast<uint4*>(Bs[cur ^ 1] + off) = pb[it];
            }
            __syncthreads();
        }
    }

    const int q    = lane >> 2;
    const int tcol = (lane & 3) << 1;
    const int lrow = (wm << 4) + q;      // local row 0..63 (lo); +8 = hi
    const int mlo  = m0 + lrow;
    const int mhi  = mlo + 8;
    if (side == 0) {
        float2 s2[4], t2[4];
        #pragma unroll
        for (int nt = 0; nt < 4; ++nt) {
            const int col = (wn << 5) + (nt << 3) + tcol;
            s2[nt] = *reinterpret_cast<const float2*>(a_src + col);
            t2[nt] = *reinterpret_cast<const float2*>(a_tgt + col);
        }
        float ssl = 0.f, stl = 0.f, ssh = 0.f, sth = 0.f;
        #pragma unroll
        for (int nt = 0; nt < 4; ++nt) {
            const float* c = acc[nt];
            const int col = (wn << 5) + (nt << 3) + tcol;
            __half2 hl = __floats2half2_rn(c[0], c[1]);
            __half2 hh = __floats2half2_rn(c[2], c[3]);
            *reinterpret_cast<unsigned*>(g_proj2h + (size_t)mlo * F2C + col)
                = *reinterpret_cast<unsigned*>(&hl);
            *reinterpret_cast<unsigned*>(g_proj2h + (size_t)mhi * F2C + col)
                = *reinterpret_cast<unsigned*>(&hh);
            ssl += c[0]*s2[nt].x + c[1]*s2[nt].y;
            stl += c[0]*t2[nt].x + c[1]*t2[nt].y;
            ssh += c[2]*s2[nt].x + c[3]*s2[nt].y;
            sth += c[2]*t2[nt].x + c[3]*t2[nt].y;
        }
        #pragma unroll
        for (int d = 1; d < 4; d <<= 1) {
            ssl += __shfl_xor_sync(0xffffffffu, ssl, d);
            stl += __shfl_xor_sync(0xffffffffu, stl, d);
            ssh += __shfl_xor_sync(0xffffffffu, ssh, d);
            sth += __shfl_xor_sync(0xffffffffu, sth, d);
        }
        if (wn == 1 && (lane & 3) == 0) {
            sred_ss[lrow] = ssl; sred_ss[lrow + 8] = ssh;
            sred_st[lrow] = stl; sred_st[lrow + 8] = sth;
        }
        __syncthreads();
        if (wn == 0 && (lane & 3) == 0) {
            g_ssrc2[mlo] = ssl + sred_ss[lrow];
            g_ssrc2[mhi] = ssh + sred_ss[lrow + 8];
            g_stgt2[mlo] = stl + sred_st[lrow];
            g_stgt2[mhi] = sth + sred_st[lrow + 8];
        }
    } else {
        #pragma unroll
        for (int nt = 0; nt < 4; ++nt) {
            const float* c = acc[nt];
            const int col = (wn << 5) + (nt << 3) + tcol;
            *reinterpret_cast<float2*>(g_skip2 + (size_t)mlo * F2C + col)
                = make_float2(c[0], c[1]);
            *reinterpret_cast<float2*>(g_skip2 + (size_t)mhi * F2C + col)
                = make_float2(c[2], c[3]);
        }
    }
}

// ========== layer-2 attention: 2 warps per row, no-max softmax =============
__global__ void __launch_bounds__(256) att2_kernel(
    const float* __restrict__ bias, float* __restrict__ out) {
    __shared__ int     noff[4][MAXN];
    __shared__ __half2 wts2[4][MAXN];
    __shared__ float2  spart[4][32];

    const int b    = blockIdx.y;
    const int tid  = threadIdx.x;
    const int lane = tid & 31;
    const int wid  = tid >> 5;           // 0..7
    const int rp   = wid >> 1;           // row slot 0..3
    const int sub  = wid & 1;            // half of neighbor list
    const int i    = (blockIdx.x << 2) + rp;
    const int row  = b * NND + i;
    const int brow = b * NND;

    const int cnt = g_cnt[row];
    if (sub == 0) {
        for (int n = lane; n < cnt; n += 32)
            noff[rp][n] = (brow + g_nbrs[(size_t)row * MAXN + n]) << 5;
        __syncwarp();
        const float si = g_ssrc2[row];
        float e[4];
        float sum = 0.f;
        #pragma unroll
        for (int s = 0; s < 4; ++s) {
            int n = lane + (s << 5);
            float ex = 0.f;
            if (n < cnt) {
                float t = si + g_stgt2[noff[rp][n] >> 5];
                t = (t > 0.f) ? t : 0.2f * t;
                ex = __expf(t);
            }
            e[s] = ex;
            sum += ex;
        }
        #pragma unroll
        for (int d = 16; d; d >>= 1)
            sum += __shfl_xor_sync(0xffffffffu, sum, d);
        float inv = 1.0f / sum;
        #pragma unroll
        for (int s = 0; s < 4; ++s) {
            int n = lane + (s << 5);
            if (n < cnt) wts2[rp][n] = __float2half2_rn(e[s] * inv);
        }
    }
    __syncthreads();

    const int half = (cnt + 1) >> 1;
    const int lo = sub ? half : 0;
    const int hi = sub ? cnt : half;
    const unsigned* __restrict__ ph =
        reinterpret_cast<const unsigned*>(g_proj2h);
    const __half2 z = __float2half2_rn(0.f);
    __half2 A0=z, A1=z, A2=z, A3=z;
    int n = lo;
    for (; n + 3 < hi; n += 4) {
        int o0 = noff[rp][n],   o1 = noff[rp][n+1];
        int o2 = noff[rp][n+2], o3 = noff[rp][n+3];
        __half2 w0 = wts2[rp][n],   w1 = wts2[rp][n+1];
        __half2 w2 = wts2[rp][n+2], w3 = wts2[rp][n+3];
        unsigned r0 = ph[o0 + lane];
        unsigned r1 = ph[o1 + lane];
        unsigned r2 = ph[o2 + lane];
        unsigned r3 = ph[o3 + lane];
        A0 = __hfma2(w0, *reinterpret_cast<__half2*>(&r0), A0);
        A1 = __hfma2(w1, *reinterpret_cast<__half2*>(&r1), A1);
        A2 = __hfma2(w2, *reinterpret_cast<__half2*>(&r2), A2);
        A3 = __hfma2(w3, *reinterpret_cast<__half2*>(&r3), A3);
    }
    for (; n < hi; ++n) {
        int o = noff[rp][n];
        __half2 w = wts2[rp][n];
        unsigned r = ph[o + lane];
        A0 = __hfma2(w, *reinterpret_cast<__half2*>(&r), A0);
    }
    float2 f0 = __half22float2(A0), f1 = __half22float2(A1);
    float2 f2 = __half22float2(A2), f3 = __half22float2(A3);
    float2 f = make_float2((f0.x + f1.x) + (f2.x + f3.x),
                           (f0.y + f1.y) + (f2.y + f3.y));
    if (sub == 1) spart[rp][lane] = f;
    __syncthreads();
    if (sub == 0) {
        float2 g = spart[rp][lane];
        const int p = lane << 1;
        float2 sk = *reinterpret_cast<const float2*>(g_skip2 + (size_t)row * F2C + p);
        float2 bb = *reinterpret_cast<const float2*>(bias + p);
        *reinterpret_cast<float2*>(out + (size_t)row * F2C + p)
            = make_float2(f.x + g.x + sk.x + bb.x,
                          f.y + g.y + sk.y + bb.y);
    }
}

// ---------------------------------------------------------------------------
extern "C" void kernel_launch(void* const* d_in, const int* in_sizes, int n_in,
                              void* d_out, int out_size) {
    const float* x     = (const float*)d_in[0];
    const float* adj   = (const float*)d_in[1];
    const float* W1    = (const float*)d_in[2];
    const float* asrc1 = (const float*)d_in[3];
    const float* atgt1 = (const float*)d_in[4];
    const float* Wsk1  = (const float*)d_in[5];
    const float* b1    = (const float*)d_in[6];
    const float* W2    = (const float*)d_in[7];
    const float* asrc2 = (const float*)d_in[8];
    const float* atgt2 = (const float*)d_in[9];
    const float* Wsk2  = (const float*)d_in[10];
    const float* b2    = (const float*)d_in[11];
    float* out = (float*)d_out;

    // 0a/0b. fp32 -> fp16 conversion
    prep_x<<<512, 256>>>(x);
    prep_w<<<192, 256>>>(W1, Wsk1, W2, Wsk2);
    // 1. fused: layer-1 tensor-core GEMM (+fp16 proj, +scores) ∥ nbr build
    fused1<<<256 + MROW, 256>>>(asrc1, atgt1, adj);
    // 2. layer-1 sparse attention (prefetched MLP=8 gather)  [profiled idx 3]
    att1_kernel<<<dim3(NND, BSZ), 128>>>(b1);
    // 3. layer-2 tensor-core GEMM (8 warps, double-buffered), fused epilogue
    gemm2_kernel<<<dim3(2, 64), 256>>>(asrc2, atgt2);
    // 4. layer-2 sparse attention + skip + bias
    att2_kernel<<<dim3(NND / 4, BSZ), 256>>>(b2, out);
}

// round 16
// speedup vs baseline: 1.0312x; 1.0312x over previous
#include <cuda_runtime.h>
#include <cuda_fp16.h>
#include <math.h>

// Problem constants
#define BSZ  2
#define NND  2048
#define FIN  128
#define H1C  8
#define HF1  512      // H1*F1
#define F2C  64
#define MROW 4096     // BSZ*NND
#define MAXN 128      // neighbor cap (binomial mean ~41)

// ---------------- scratch (static device memory; no allocs) ----------------
__device__ __half g_wh1  [1024*FIN];        // fp16 [W1 ; Wsk1]
__device__ __half g_wh2  [128*HF1];         // fp16 [W2 ; Wsk2]
__device__ __half g_proj1h[MROW*HF1];       // fp16 proj1 (gather operand)
__device__ float  g_skip1 [MROW*HF1];
__device__ __half g_h1h  [MROW*HF1];        // fp16 h1 (gemm2 A operand)
__device__ __half g_proj2h[MROW*F2C];
__device__ float  g_skip2 [MROW*F2C];
__device__ float  g_ssrc1 [MROW*H1C];       // [m][h]
__device__ float  g_stgt1 [MROW*H1C];       // [m][h]  (row-contiguous, 32B)
__device__ float  g_ssrc2 [MROW];
__device__ float  g_stgt2 [MROW];
__device__ int    g_nbrs[MROW*MAXN];
__device__ int    g_cnt [MROW];

// ---------------- mma / ldmatrix helpers -----------------------------------
__device__ __forceinline__ void mma_16816(float c[4], const unsigned a[4],
                                          unsigned b0, unsigned b1) {
    asm volatile(
        "mma.sync.aligned.m16n8k16.row.col.f32.f16.f16.f32 "
        "{%0,%1,%2,%3}, {%4,%5,%6,%7}, {%8,%9}, {%0,%1,%2,%3};"
        : "+f"(c[0]), "+f"(c[1]), "+f"(c[2]), "+f"(c[3])
        : "r"(a[0]), "r"(a[1]), "r"(a[2]), "r"(a[3]), "r"(b0), "r"(b1));
}
__device__ __forceinline__ void ldsm4(unsigned r[4], const void* p) {
    unsigned addr = (unsigned)__cvta_generic_to_shared(p);
    asm volatile("ldmatrix.sync.aligned.m8n8.x4.shared.b16 {%0,%1,%2,%3}, [%4];"
                 : "=r"(r[0]), "=r"(r[1]), "=r"(r[2]), "=r"(r[3]) : "r"(addr));
}

// ---------------- prep_w: fp32 -> fp16 weights only ------------------------
__device__ __forceinline__ void cvt_store(const float4* s, __half* d) {
    float4 v = *s;
    __half2 h01 = __floats2half2_rn(v.x, v.y);
    __half2 h23 = __floats2half2_rn(v.z, v.w);
    uint2 pk;
    pk.x = *reinterpret_cast<unsigned*>(&h01);
    pk.y = *reinterpret_cast<unsigned*>(&h23);
    *reinterpret_cast<uint2*>(d) = pk;
}
__global__ void prep_w(const float* __restrict__ W1, const float* __restrict__ Ws1,
                       const float* __restrict__ W2, const float* __restrict__ Ws2) {
    int i = blockIdx.x * blockDim.x + threadIdx.x;   // 49152 float4
    const float4* s; __half* d;
    if      (i < 16384) { s = (const float4*)W1  + i;           d = g_wh1 + i*4; }
    else if (i < 32768) { s = (const float4*)Ws1 + (i-16384);   d = g_wh1 + 65536 + (i-16384)*4; }
    else if (i < 40960) { s = (const float4*)W2  + (i-32768);   d = g_wh2 + (i-32768)*4; }
    else                { s = (const float4*)Ws2 + (i-40960);   d = g_wh2 + 32768 + (i-40960)*4; }
    cvt_store(s, d);
}

// ============ fused: layer-1 mma GEMM (+fp16 proj, +scores) ∥ nbr build ====
// A operand converted fp32->fp16 inline (no prep_x pass).
__global__ void __launch_bounds__(256) fused1(
    const float* __restrict__ x,
    const float* __restrict__ asrc, const float* __restrict__ atgt,
    const float* __restrict__ adj) {
    __shared__ __align__(16) char As[16384];   // 128 rows x 128B, swizzled
    __shared__ __align__(16) char Bs[16384];
    __shared__ unsigned int words[64];

    const int tid  = threadIdx.x;
    const int lane = tid & 31;
    const int wid  = tid >> 5;

    if (blockIdx.x >= 256) {
        // ---------------- neighbor build (batched loads, MLP=8) ------------
        const int bid = (int)blockIdx.x - 256;
        const int i   = bid & (NND - 1);
        const int b   = bid >> 11;
        const int row = b * NND + i;
        const size_t arow = (size_t)row * NND;
        float av[8];
        #pragma unroll
        for (int it = 0; it < 8; ++it)
            av[it] = adj[arow + (((wid << 3) + it) << 5) + lane];
        #pragma unroll
        for (int it = 0; it < 8; ++it) {
            unsigned m = __ballot_sync(0xffffffffu, av[it] != 0.0f);
            if (lane == 0) words[(wid << 3) + it] = m;
        }
        __syncthreads();
        if (wid == 0) {
            int base = 0;
            #pragma unroll
            for (int r = 0; r < 2; ++r) {
                unsigned w = words[(r << 5) + lane];
                int c = __popc(w);
                int inc = c;
                #pragma unroll
                for (int d = 1; d < 32; d <<= 1) {
                    int v = __shfl_up_sync(0xffffffffu, inc, d);
                    if (lane >= d) inc += v;
                }
                int start = base + inc - c;
                int jb = ((r << 5) + lane) << 5;
                while (w) {
                    int bit = __ffs(w) - 1;
                    w &= w - 1;
                    if (start < MAXN) g_nbrs[(size_t)row * MAXN + start] = jb + bit;
                    ++start;
                }
                base += __shfl_sync(0xffffffffu, inc, 31);
            }
            if (lane == 0) g_cnt[row] = (base < MAXN) ? base : MAXN;
        }
        return;
    }

    // ---------------- mma GEMM tile ----------------
    const int bx = blockIdx.x & 7;
    const int by = blockIdx.x >> 3;
    const int m0 = by << 7;
    const int n0 = bx << 7;
    const int wm = wid & 3;              // 4 m-warps (32 rows each)
    const int wn = wid >> 2;             // 2 n-warps (64 cols each)

    float acc[2][8][4];
    #pragma unroll
    for (int mt = 0; mt < 2; ++mt)
        #pragma unroll
        for (int nt = 0; nt < 8; ++nt)
            #pragma unroll
            for (int c = 0; c < 4; ++c) acc[mt][nt][c] = 0.f;

    const uint4* __restrict__ wg = reinterpret_cast<const uint4*>(g_wh1);

    #pragma unroll
    for (int kc = 0; kc < 2; ++kc) {
        #pragma unroll
        for (int it = 0; it < 4; ++it) {
            int idx = tid + (it << 8);           // 0..1023
            int r   = idx >> 3;                  // row 0..127
            int cb  = idx & 7;                   // 16B fp16 chunk 0..7
            // A: convert fp32 x inline (same __floats2half2_rn as prep did)
            const float4* xs = reinterpret_cast<const float4*>(
                x + (size_t)(m0 + r) * FIN + kc * 64 + (cb << 3));
            float4 v0 = xs[0], v1 = xs[1];
            __half2 h0 = __floats2half2_rn(v0.x, v0.y);
            __half2 h1 = __floats2half2_rn(v0.z, v0.w);
            __half2 h2 = __floats2half2_rn(v1.x, v1.y);
            __half2 h3 = __floats2half2_rn(v1.z, v1.w);
            uint4 a;
            a.x = *reinterpret_cast<unsigned*>(&h0);
            a.y = *reinterpret_cast<unsigned*>(&h1);
            a.z = *reinterpret_cast<unsigned*>(&h2);
            a.w = *reinterpret_cast<unsigned*>(&h3);
            *reinterpret_cast<uint4*>(As + r * 128 + ((cb << 4) ^ ((r & 7) << 4))) = a;
            uint4 b = wg[(size_t)(n0 + r) * 16 + kc * 8 + cb];
            *reinterpret_cast<uint4*>(Bs + r * 128 + ((cb << 4) ^ ((r & 7) << 4))) = b;
        }
        __syncthreads();

        #pragma unroll
        for (int ks = 0; ks < 4; ++ks) {
            const int kb = (ks << 5) + (lane & 16);
            unsigned af[2][4], bf[4][4];
            #pragma unroll
            for (int mt = 0; mt < 2; ++mt) {
                int r = (wm << 5) + (mt << 4) + (lane & 15);
                ldsm4(af[mt], As + r * 128 + (kb ^ ((r & 7) << 4)));
            }
            #pragma unroll
            for (int bt = 0; bt < 4; ++bt) {
                int r = (wn << 6) + (bt << 4) + (lane & 15);
                ldsm4(bf[bt], Bs + r * 128 + (kb ^ ((r & 7) << 4)));
            }
            #pragma unroll
            for (int mt = 0; mt < 2; ++mt)
                #pragma unroll
                for (int nt = 0; nt < 8; ++nt)
                    mma_16816(acc[mt][nt], af[mt],
                              bf[nt >> 1][nt & 1], bf[nt >> 1][2 + (nt & 1)]);
        }
        __syncthreads();
    }

    // ---------------- epilogue ----------------
    const int q    = lane >> 2;          // row-in-group
    const int tcol = (lane & 3) << 1;    // col pair base
    if (bx < 4) {
        const int h = (bx << 1) + wn;    // head covered by this warp
        float2 s2[8], t2[8];
        #pragma unroll
        for (int nt = 0; nt < 8; ++nt) {
            s2[nt] = *reinterpret_cast<const float2*>(asrc + h * 64 + (nt << 3) + tcol);
            t2[nt] = *reinterpret_cast<const float2*>(atgt + h * 64 + (nt << 3) + tcol);
        }
        #pragma unroll
        for (int mt = 0; mt < 2; ++mt) {
            const int mlo = m0 + (wm << 5) + (mt << 4) + q;
            const int mhi = mlo + 8;
            float ssl = 0.f, stl = 0.f, ssh = 0.f, sth = 0.f;
            #pragma unroll
            for (int nt = 0; nt < 8; ++nt) {
                const float* c = acc[mt][nt];
                const int col = h * 64 + (nt << 3) + tcol;
                __half2 hl = __floats2half2_rn(c[0], c[1]);
                __half2 hh = __floats2half2_rn(c[2], c[3]);
                *reinterpret_cast<unsigned*>(g_proj1h + (size_t)mlo * HF1 + col)
                    = *reinterpret_cast<unsigned*>(&hl);
                *reinterpret_cast<unsigned*>(g_proj1h + (size_t)mhi * HF1 + col)
                    = *reinterpret_cast<unsigned*>(&hh);
                ssl += c[0]*s2[nt].x + c[1]*s2[nt].y;
                stl += c[0]*t2[nt].x + c[1]*t2[nt].y;
                ssh += c[2]*s2[nt].x + c[3]*s2[nt].y;
                sth += c[2]*t2[nt].x + c[3]*t2[nt].y;
            }
            #pragma unroll
            for (int d = 1; d < 4; d <<= 1) {
                ssl += __shfl_xor_sync(0xffffffffu, ssl, d);
                stl += __shfl_xor_sync(0xffffffffu, stl, d);
                ssh += __shfl_xor_sync(0xffffffffu, ssh, d);
                sth += __shfl_xor_sync(0xffffffffu, sth, d);
            }
            if ((lane & 3) == 0) {
                g_ssrc1[mlo * H1C + h] = ssl;
                g_ssrc1[mhi * H1C + h] = ssh;
                g_stgt1[mlo * H1C + h] = stl;
                g_stgt1[mhi * H1C + h] = sth;
            }
        }
    } else {
        #pragma unroll
        for (int mt = 0; mt < 2; ++mt) {
            const int mlo = m0 + (wm << 5) + (mt << 4) + q;
            const int mhi = mlo + 8;
            #pragma unroll
            for (int nt = 0; nt < 8; ++nt) {
                const float* c = acc[mt][nt];
                const int col = ((bx - 4) << 7) + (wn << 6) + (nt << 3) + tcol;
                *reinterpret_cast<float2*>(g_skip1 + (size_t)mlo * HF1 + col)
                    = make_float2(c[0], c[1]);
                *reinterpret_cast<float2*>(g_skip1 + (size_t)mhi * HF1 + col)
                    = make_float2(c[2], c[3]);
            }
        }
    }
}

// ========== layer-1 attention (R14 best): smem score vectors + HFMA2 =======
__global__ void __launch_bounds__(128) att1_kernel(const float* __restrict__ bias) {
    __shared__ int     noff[MAXN];              // (brow+j)<<7 (uint2 row base)
    __shared__ float   stv[MAXN][9];            // 8 head scores + pad
    __shared__ __half2 wts2[H1C][MAXN];

    const int i    = blockIdx.x;
    const int b    = blockIdx.y;
    const int tid  = threadIdx.x;
    const int lane = tid & 31;
    const int wid  = tid >> 5;
    const int row  = b * NND + i;
    const int brow = b * NND;

    const int cnt = g_cnt[row];
    for (int n = tid; n < cnt; n += 128) {
        int j = g_nbrs[(size_t)row * MAXN + n];
        noff[n] = (brow + j) << 7;
        const float4* sp = reinterpret_cast<const float4*>(
            g_stgt1 + (size_t)(brow + j) * H1C);
        float4 s0 = sp[0];
        float4 s1 = sp[1];
        stv[n][0] = s0.x; stv[n][1] = s0.y; stv[n][2] = s0.z; stv[n][3] = s0.w;
        stv[n][4] = s1.x; stv[n][5] = s1.y; stv[n][6] = s1.z; stv[n][7] = s1.w;
    }
    __syncthreads();

    #pragma unroll
    for (int hh = 0; hh < 2; ++hh) {
        const int h = (wid << 1) + hh;
        const float si = g_ssrc1[row * H1C + h];
        float e[4];
        float mx = -3.0e38f;
        #pragma unroll
        for (int s = 0; s < 4; ++s) {
            int n = lane + (s << 5);
            float v = -3.0e38f;
            if (n < cnt) {
                float t = si + stv[n][h];
                v = (t > 0.f) ? t : 0.2f * t;       // leaky_relu(0.2)
            }
            e[s] = v;
            mx = fmaxf(mx, v);
        }
        #pragma unroll
        for (int d = 16; d; d >>= 1)
            mx = fmaxf(mx, __shfl_xor_sync(0xffffffffu, mx, d));
        float sum = 0.f;
        #pragma unroll
        for (int s = 0; s < 4; ++s) {
            float ex = __expf(e[s] - mx);           // inactive -> 0
            e[s] = ex;
            sum += ex;
        }
        #pragma unroll
        for (int d = 16; d; d >>= 1)
            sum += __shfl_xor_sync(0xffffffffu, sum, d);
        float inv = 1.0f / sum;
        #pragma unroll
        for (int s = 0; s < 4; ++s) {
            int n = lane + (s << 5);
            if (n < cnt) wts2[h][n] = __float2half2_rn(e[s] * inv);
        }
    }
    __syncthreads();

    // gather: thread owns 4 features; uint2 index within row == tid
    const int h = tid >> 4;
    const uint2* __restrict__ ph = reinterpret_cast<const uint2*>(g_proj1h);
    const __half2 z = __float2half2_rn(0.f);
    __half2 a0=z, b0=z, a1=z, b1=z, a2=z, b2=z, a3=z, b3=z;
    int n = 0;
    for (; n + 3 < cnt; n += 4) {
        int o0 = noff[n], o1 = noff[n+1], o2 = noff[n+2], o3 = noff[n+3];
        __half2 w0 = wts2[h][n],   w1 = wts2[h][n+1];
        __half2 w2 = wts2[h][n+2], w3 = wts2[h][n+3];
        uint2 r0 = ph[o0 + tid];
        uint2 r1 = ph[o1 + tid];
        uint2 r2 = ph[o2 + tid];
        uint2 r3 = ph[o3 + tid];
        a0 = __hfma2(w0, *reinterpret_cast<__half2*>(&r0.x), a0);
        b0 = __hfma2(w0, *reinterpret_cast<__half2*>(&r0.y), b0);
        a1 = __hfma2(w1, *reinterpret_cast<__half2*>(&r1.x), a1);
        b1 = __hfma2(w1, *reinterpret_cast<__half2*>(&r1.y), b1);
        a2 = __hfma2(w2, *reinterpret_cast<__half2*>(&r2.x), a2);
        b2 = __hfma2(w2, *reinterpret_cast<__half2*>(&r2.y), b2);
        a3 = __hfma2(w3, *reinterpret_cast<__half2*>(&r3.x), a3);
        b3 = __hfma2(w3, *reinterpret_cast<__half2*>(&r3.y), b3);
    }
    for (; n < cnt; ++n) {
        int o = noff[n];
        __half2 w = wts2[h][n];
        uint2 r = ph[o + tid];
        a0 = __hfma2(w, *reinterpret_cast<__half2*>(&r.x), a0);
        b0 = __hfma2(w, *reinterpret_cast<__half2*>(&r.y), b0);
    }
    float2 fa0 = __half22float2(a0), fa1 = __half22float2(a1);
    float2 fa2 = __half22float2(a2), fa3 = __half22float2(a3);
    float2 fb0 = __half22float2(b0), fb1 = __half22float2(b1);
    float2 fb2 = __half22float2(b2), fb3 = __half22float2(b3);
    const int p = tid << 2;
    float4 sk = *reinterpret_cast<const float4*>(g_skip1 + (size_t)row * HF1 + p);
    float4 bb = *reinterpret_cast<const float4*>(bias + p);
    float4 o;
    o.x = (fa0.x + fa1.x) + (fa2.x + fa3.x) + sk.x + bb.x;
    o.y = (fa0.y + fa1.y) + (fa2.y + fa3.y) + sk.y + bb.y;
    o.z = (fb0.x + fb1.x) + (fb2.x + fb3.x) + sk.z + bb.z;
    o.w = (fb0.y + fb1.y) + (fb2.y + fb3.y) + sk.w + bb.w;
    o.x = (o.x > 0.f) ? o.x : (__expf(o.x) - 1.f);
    o.y = (o.y > 0.f) ? o.y : (__expf(o.y) - 1.f);
    o.z = (o.z > 0.f) ? o.z : (__expf(o.z) - 1.f);
    o.w = (o.w > 0.f) ? o.w : (__expf(o.w) - 1.f);
    __half2 h01 = __floats2half2_rn(o.x, o.y);
    __half2 h23 = __floats2half2_rn(o.z, o.w);
    uint2 pk;
    pk.x = *reinterpret_cast<unsigned*>(&h01);
    pk.y = *reinterpret_cast<unsigned*>(&h23);
    *reinterpret_cast<uint2*>(g_h1h + (size_t)row * HF1 + p) = pk;
}

// ===== layer-2 mma GEMM: 8 warps (16x32 warp tile), double-buffered ========
__global__ void __launch_bounds__(256) gemm2_kernel(
    const float* __restrict__ a_src, const float* __restrict__ a_tgt) {
    __shared__ __align__(16) char As[2][8192];   // 64 rows x 128B each
    __shared__ __align__(16) char Bs[2][8192];
    __shared__ float sred_ss[64], sred_st[64];

    const int tid  = threadIdx.x;
    const int lane = tid & 31;
    const int wid  = tid >> 5;           // 0..7
    const int wm   = wid & 3;            // 16-row group
    const int wn   = wid >> 2;           // 32-col group
    const int m0   = blockIdx.y << 6;
    const int side = blockIdx.x;         // 0 proj, 1 skip

    float acc[4][4];
    #pragma unroll
    for (int nt = 0; nt < 4; ++nt)
        #pragma unroll
        for (int c = 0; c < 4; ++c) acc[nt][c] = 0.f;

    const uint4* __restrict__ ag = reinterpret_cast<const uint4*>(g_h1h);
    const uint4* __restrict__ bg = reinterpret_cast<const uint4*>(g_wh2);

    const int fr = tid >> 3;             // 0..31; rows fr, fr+32
    const int fc = tid & 7;              // 16B chunk 0..7
    uint4 pa[2], pb[2];

    #pragma unroll
    for (int it = 0; it < 2; ++it) {
        int r = fr + (it << 5);
        pa[it] = ag[(size_t)(m0 + r) * 64 + fc];
        pb[it] = bg[(size_t)(side * 64 + r) * 64 + fc];
    }
    #pragma unroll
    for (int it = 0; it < 2; ++it) {
        int r = fr + (it << 5);
        int off = r * 128 + ((fc << 4) ^ ((r & 7) << 4));
        *reinterpret_cast<uint4*>(As[0] + off) = pa[it];
        *reinterpret_cast<uint4*>(Bs[0] + off) = pb[it];
    }
    __syncthreads();

    #pragma unroll
    for (int kc = 0; kc < 8; ++kc) {
        const int cur = kc & 1;
        if (kc < 7) {
            #pragma unroll
            for (int it = 0; it < 2; ++it) {
                int r = fr + (it << 5);
                pa[it] = ag[(size_t)(m0 + r) * 64 + (kc + 1) * 8 + fc];
                pb[it] = bg[(size_t)(side * 64 + r) * 64 + (kc + 1) * 8 + fc];
            }
        }
        #pragma unroll
        for (int ks = 0; ks < 4; ++ks) {
            const int kb = (ks << 5) + (lane & 16);
            unsigned af[4], bf[2][4];
            {
                int r = (wm << 4) + (lane & 15);
                ldsm4(af, As[cur] + r * 128 + (kb ^ ((r & 7) << 4)));
            }
            #pragma unroll
            for (int bt = 0; bt < 2; ++bt) {
                int r = (wn << 5) + (bt << 4) + (lane & 15);
                ldsm4(bf[bt], Bs[cur] + r * 128 + (kb ^ ((r & 7) << 4)));
            }
            #pragma unroll
            for (int nt = 0; nt < 4; ++nt)
                mma_16816(acc[nt], af,
                          bf[nt >> 1][nt & 1], bf[nt >> 1][2 + (nt & 1)]);
        }
        if (kc < 7) {
            #pragma unroll
            for (int it = 0; it < 2; ++it) {
                int r = fr + (it << 5);
                int off = r * 128 + ((fc << 4) ^ ((r & 7) << 4));
                *reinterpret_cast<uint4*>(As[cur ^ 1] + off) = pa[it];
                *reinterpret_cast<uint4*>(Bs[cur ^ 1] + off) = pb[it];
            }
            __syncthreads();
        }
    }

    const int q    = lane >> 2;
    const int tcol = (lane & 3) << 1;
    const int lrow = (wm << 4) + q;      // local row 0..63 (lo); +8 = hi
    const int mlo  = m0 + lrow;
    const int mhi  = mlo + 8;
    if (side == 0) {
        float2 s2[4], t2[4];
        #pragma unroll
        for (int nt = 0; nt < 4; ++nt) {
            const int col = (wn << 5) + (nt << 3) + tcol;
            s2[nt] = *reinterpret_cast<const float2*>(a_src + col);
            t2[nt] = *reinterpret_cast<const float2*>(a_tgt + col);
        }
        float ssl = 0.f, stl = 0.f, ssh = 0.f, sth = 0.f;
        #pragma unroll
        for (int nt = 0; nt < 4; ++nt) {
            const float* c = acc[nt];
            const int col = (wn << 5) + (nt << 3) + tcol;
            __half2 hl = __floats2half2_rn(c[0], c[1]);
            __half2 hh = __floats2half2_rn(c[2], c[3]);
            *reinterpret_cast<unsigned*>(g_proj2h + (size_t)mlo * F2C + col)
                = *reinterpret_cast<unsigned*>(&hl);
            *reinterpret_cast<unsigned*>(g_proj2h + (size_t)mhi * F2C + col)
                = *reinterpret_cast<unsigned*>(&hh);
            ssl += c[0]*s2[nt].x + c[1]*s2[nt].y;
            stl += c[0]*t2[nt].x + c[1]*t2[nt].y;
            ssh += c[2]*s2[nt].x + c[3]*s2[nt].y;
            sth += c[2]*t2[nt].x + c[3]*t2[nt].y;
        }
        #pragma unroll
        for (int d = 1; d < 4; d <<= 1) {
            ssl += __shfl_xor_sync(0xffffffffu, ssl, d);
            stl += __shfl_xor_sync(0xffffffffu, stl, d);
            ssh += __shfl_xor_sync(0xffffffffu, ssh, d);
            sth += __shfl_xor_sync(0xffffffffu, sth, d);
        }
        if (wn == 1 && (lane & 3) == 0) {
            sred_ss[lrow] = ssl; sred_ss[lrow + 8] = ssh;
            sred_st[lrow] = stl; sred_st[lrow + 8] = sth;
        }
        __syncthreads();
        if (wn == 0 && (lane & 3) == 0) {
            g_ssrc2[mlo] = ssl + sred_ss[lrow];
            g_ssrc2[mhi] = ssh + sred_ss[lrow + 8];
            g_stgt2[mlo] = stl + sred_st[lrow];
            g_stgt2[mhi] = sth + sred_st[lrow + 8];
        }
    } else {
        #pragma unroll
        for (int nt = 0; nt < 4; ++nt) {
            const float* c = acc[nt];
            const int col = (wn << 5) + (nt << 3) + tcol;
            *reinterpret_cast<float2*>(g_skip2 + (size_t)mlo * F2C + col)
                = make_float2(c[0], c[1]);
            *reinterpret_cast<float2*>(g_skip2 + (size_t)mhi * F2C + col)
                = make_float2(c[2], c[3]);
        }
    }
}

// ========== layer-2 attention (R14 best): 2 warps per row ==================
__global__ void __launch_bounds__(256) att2_kernel(
    const float* __restrict__ bias, float* __restrict__ out) {
    __shared__ int     noff[4][MAXN];
    __shared__ __half2 wts2[4][MAXN];
    __shared__ float2  spart[4][32];

    const int b    = blockIdx.y;
    const int tid  = threadIdx.x;
    const int lane = tid & 31;
    const int wid  = tid >> 5;           // 0..7
    const int rp   = wid >> 1;           // row slot 0..3
    const int sub  = wid & 1;            // half of neighbor list
    const int i    = (blockIdx.x << 2) + rp;
    const int row  = b * NND + i;
    const int brow = b * NND;

    const int cnt = g_cnt[row];
    if (sub == 0) {
        for (int n = lane; n < cnt; n += 32)
            noff[rp][n] = (brow + g_nbrs[(size_t)row * MAXN + n]) << 5;
        __syncwarp();
        const float si = g_ssrc2[row];
        float e[4];
        float mx = -3.0e38f;
        #pragma unroll
        for (int s = 0; s < 4; ++s) {
            int n = lane + (s << 5);
            float v = -3.0e38f;
            if (n < cnt) {
                float t = si + g_stgt2[noff[rp][n] >> 5];
                v = (t > 0.f) ? t : 0.2f * t;
            }
            e[s] = v;
            mx = fmaxf(mx, v);
        }
        #pragma unroll
        for (int d = 16; d; d >>= 1)
            mx = fmaxf(mx, __shfl_xor_sync(0xffffffffu, mx, d));
        float sum = 0.f;
        #pragma unroll
        for (int s = 0; s < 4; ++s) {
            float ex = __expf(e[s] - mx);
            e[s] = ex;
            sum += ex;
        }
        #pragma unroll
        for (int d = 16; d; d >>= 1)
            sum += __shfl_xor_sync(0xffffffffu, sum, d);
        float inv = 1.0f / sum;
        #pragma unroll
        for (int s = 0; s < 4; ++s) {
            int n = lane + (s << 5);
            if (n < cnt) wts2[rp][n] = __float2half2_rn(e[s] * inv);
        }
    }
    __syncthreads();

    const int half = (cnt + 1) >> 1;
    const int lo = sub ? half : 0;
    const int hi = sub ? cnt : half;
    const unsigned* __restrict__ ph =
        reinterpret_cast<const unsigned*>(g_proj2h);
    const __half2 z = __float2half2_rn(0.f);
    __half2 A0=z, A1=z, A2=z, A3=z;
    int n = lo;
    for (; n + 3 < hi; n += 4) {
        int o0 = noff[rp][n],   o1 = noff[rp][n+1];
        int o2 = noff[rp][n+2], o3 = noff[rp][n+3];
        __half2 w0 = wts2[rp][n],   w1 = wts2[rp][n+1];
        __half2 w2 = wts2[rp][n+2], w3 = wts2[rp][n+3];
        unsigned r0 = ph[o0 + lane];
        unsigned r1 = ph[o1 + lane];
        unsigned r2 = ph[o2 + lane];
        unsigned r3 = ph[o3 + lane];
        A0 = __hfma2(w0, *reinterpret_cast<__half2*>(&r0), A0);
        A1 = __hfma2(w1, *reinterpret_cast<__half2*>(&r1), A1);
        A2 = __hfma2(w2, *reinterpret_cast<__half2*>(&r2), A2);
        A3 = __hfma2(w3, *reinterpret_cast<__half2*>(&r3), A3);
    }
    for (; n < hi; ++n) {
        int o = noff[rp][n];
        __half2 w = wts2[rp][n];
        unsigned r = ph[o + lane];
        A0 = __hfma2(w, *reinterpret_cast<__half2*>(&r), A0);
    }
    float2 f0 = __half22float2(A0), f1 = __half22float2(A1);
    float2 f2 = __half22float2(A2), f3 = __half22float2(A3);
    float2 f = make_float2((f0.x + f1.x) + (f2.x + f3.x),
                           (f0.y + f1.y) + (f2.y + f3.y));
    if (sub == 1) spart[rp][lane] = f;
    __syncthreads();
    if (sub == 0) {
        float2 g = spart[rp][lane];
        const int p = lane << 1;
        float2 sk = *reinterpret_cast<const float2*>(g_skip2 + (size_t)row * F2C + p);
        float2 bb = *reinterpret_cast<const float2*>(bias + p);
        *reinterpret_cast<float2*>(out + (size_t)row * F2C + p)
            = make_float2(f.x + g.x + sk.x + bb.x,
                          f.y + g.y + sk.y + bb.y);
    }
}

// ---------------------------------------------------------------------------
extern "C" void kernel_launch(void* const* d_in, const int* in_sizes, int n_in,
                              void* d_out, int out_size) {
    const float* x     = (const float*)d_in[0];
    const float* adj   = (const float*)d_in[1];
    const float* W1    = (const float*)d_in[2];
    const float* asrc1 = (const float*)d_in[3];
    const float* atgt1 = (const float*)d_in[4];
    const float* Wsk1  = (const float*)d_in[5];
    const float* b1    = (const float*)d_in[6];
    const float* W2    = (const float*)d_in[7];
    const float* asrc2 = (const float*)d_in[8];
    const float* atgt2 = (const float*)d_in[9];
    const float* Wsk2  = (const float*)d_in[10];
    const float* b2    = (const float*)d_in[11];
    float* out = (float*)d_out;

    // 0. fp32 -> fp16 weights (x converted inline in fused1)
    prep_w<<<192, 256>>>(W1, Wsk1, W2, Wsk2);
    // 1. fused: layer-1 tensor-core GEMM (+fp16 proj, +scores) ∥ nbr build
    fused1<<<256 + MROW, 256>>>(x, asrc1, atgt1, adj);
    // 2. layer-1 sparse attention (R14 best variant)
    att1_kernel<<<dim3(NND, BSZ), 128>>>(b1);
    // 3. layer-2 tensor-core GEMM (8 warps)          [profiled idx 3]
    gemm2_kernel<<<dim3(2, 64), 256>>>(asrc2, atgt2);
    // 4. layer-2 sparse attention + skip + bias
    att2_kernel<<<dim3(NND / 4, BSZ), 256>>>(b2, out);
}